// round 14
// baseline (speedup 1.0000x reference)
#include <cuda_runtime.h>

// Problem constants (fixed: B=128, C=1024, N=512, NUM_CLASSES=1024)
#define BB 128
#define CC 1024
#define NN 512
#define NC 1024
#define LCAP 48    // per-category list capacity (mean ~10, P(>48) ~ 0)
#define FLAT 16    // flat-load region (P(cnt>16) ~ 3% -> scalar tail)

// byte offsets into g_mt (row stride = BB*4 = 512 bytes = n<<9)
#define POS_SENT ((NN + 1) << 9)   // row NN+1 = 1.0 -> 1-min no-op
#define NEG_SENT (NN << 9)         // row NN   = 0.0 -> max no-op

// ---- scratch (device globals; zero-init at load; all state self-resets) ----
__device__ float    g_mt[NN + 2][BB];   // rows: 0..511 data, 512 zeros, 513 ones
__device__ int      g_head[CC];         // packed (n<<1)|isNeg (one per row)
__device__ int      g_cd[NN];           // countdown = contributors (self-resets to 0)
__device__ unsigned g_lb[NN][BB];       // fp-bit max accum (reset by finalizer)
__device__ unsigned g_ub[NN][BB];

// ============ Node 1: heads + transpose + copy ============
// grid = 512 CTAs x 128 threads; CTA cb handles head rows c0=2cb, c1=2cb+1.
__global__ void __launch_bounds__(128) k_head(
    const float* __restrict__ preds,
    const float* __restrict__ pos_head,
    const float* __restrict__ neg_head,
    const int*   __restrict__ atoms,     // jax downcasts int64 -> int32
    float*       __restrict__ out)
{
    const int cb = blockIdx.x;
    const int c0 = cb * 2, c1 = c0 + 1;
    const int t  = threadIdx.x;

    // front-batched independent loads (head masks only)
    const float4 h0 = ((const float4*)(pos_head + c0 * NN))[t];
    const float4 g0 = ((const float4*)(neg_head + c0 * NN))[t];
    const float4 h1 = ((const float4*)(pos_head + c1 * NN))[t];
    const float4 g1 = ((const float4*)(neg_head + c1 * NN))[t];

    // preds -> out copy: 64 float4 per CTA (threads 0..63 cover all 32768)
    if (t < 64)
        ((float4*)out)[cb * 64 + t] = ((const float4*)preds)[cb * 64 + t];

    // g_mt transpose gather: row n = cb, thread t = batch b
    g_mt[cb][t] = preds[t * NC + (atoms[cb] & (NC - 1))];

    // pos-sentinel row of ones (row NN stays 0 from zero-init)
    if (cb == 0) g_mt[NN + 1][t] = 1.0f;

    const int n0 = t * 4;
    { // head entry row c0 (exactly one nonzero across pos/neg head)
        int hm = -1;
        if (h0.x > 0.5f) hm = ((n0 + 0) << 1);
        if (h0.y > 0.5f) hm = ((n0 + 1) << 1);
        if (h0.z > 0.5f) hm = ((n0 + 2) << 1);
        if (h0.w > 0.5f) hm = ((n0 + 3) << 1);
        if (g0.x > 0.5f) hm = ((n0 + 0) << 1) | 1;
        if (g0.y > 0.5f) hm = ((n0 + 1) << 1) | 1;
        if (g0.z > 0.5f) hm = ((n0 + 2) << 1) | 1;
        if (g0.w > 0.5f) hm = ((n0 + 3) << 1) | 1;
        if (hm >= 0) {                        // single finder thread: race-free
            g_head[c0] = hm;
            atomicAdd(&g_cd[(hm >> 1) & (NN - 1)], 1);
        }
    }
    { // head entry row c1
        int hm = -1;
        if (h1.x > 0.5f) hm = ((n0 + 0) << 1);
        if (h1.y > 0.5f) hm = ((n0 + 1) << 1);
        if (h1.z > 0.5f) hm = ((n0 + 2) << 1);
        if (h1.w > 0.5f) hm = ((n0 + 3) << 1);
        if (g1.x > 0.5f) hm = ((n0 + 0) << 1) | 1;
        if (g1.y > 0.5f) hm = ((n0 + 1) << 1) | 1;
        if (g1.z > 0.5f) hm = ((n0 + 2) << 1) | 1;
        if (g1.w > 0.5f) hm = ((n0 + 3) << 1) | 1;
        if (hm >= 0) {
            g_head[c1] = hm;
            atomicAdd(&g_cd[(hm >> 1) & (NN - 1)], 1);
        }
    }
}

// ============ Node 2: body masks -> bmin -> scatter -> finalize ============
// grid = 1024 CTAs x 128 threads (thread = b). One row per CTA.
// pos entries feed an fmin chain (max(1-m) == 1-min(m), exact by monotone
// rounding); neg entries feed an fmax chain. Flat 16+16 sentinel-padded loads.
__global__ void __launch_bounds__(128, 7) k_body(
    const float* __restrict__ pos_body,
    const float* __restrict__ neg_body,
    const int*   __restrict__ atoms,
    float*       __restrict__ out)
{
    const int c = blockIdx.x;
    const int t = threadIdx.x;

    // front-batched loads
    const int   hm = g_head[c];
    const float4 p = ((const float4*)(pos_body + c * NN))[t];
    const float4 q = ((const float4*)(neg_body + c * NN))[t];

    __shared__ int pcnt, ncnt;
    __shared__ int posl[LCAP], negl[LCAP];
    __shared__ int s_last;
    if (t == 0) { pcnt = 0; ncnt = 0; }
    __syncthreads();

    // compact: pre-scaled byte offsets (n << 9), separate pos/neg lists
    const int n0 = t * 4;
    {
        int loc[4]; int ln = 0;
        if (p.x > 0.5f) loc[ln++] = (n0 + 0) << 9;
        if (p.y > 0.5f) loc[ln++] = (n0 + 1) << 9;
        if (p.z > 0.5f) loc[ln++] = (n0 + 2) << 9;
        if (p.w > 0.5f) loc[ln++] = (n0 + 3) << 9;
        if (ln) {
            int base = atomicAdd(&pcnt, ln);
            #pragma unroll
            for (int i = 0; i < 4; i++)
                if (i < ln && base + i < LCAP) posl[base + i] = loc[i];
        }
    }
    {
        int loc[4]; int ln = 0;
        if (q.x > 0.5f) loc[ln++] = (n0 + 0) << 9;
        if (q.y > 0.5f) loc[ln++] = (n0 + 1) << 9;
        if (q.z > 0.5f) loc[ln++] = (n0 + 2) << 9;
        if (q.w > 0.5f) loc[ln++] = (n0 + 3) << 9;
        if (ln) {
            int base = atomicAdd(&ncnt, ln);
            #pragma unroll
            for (int i = 0; i < 4; i++)
                if (i < ln && base + i < LCAP) negl[base + i] = loc[i];
        }
    }
    __syncthreads();
    const int pc = min(pcnt, LCAP);
    const int nc = min(ncnt, LCAP);
    if (t < FLAT) {                      // sentinel-pad the flat region
        if (t >= pc) posl[t] = POS_SENT;
        if (t >= nc) negl[t] = NEG_SENT;
    }
    __syncthreads();

    const char* mtb = (const char*)&g_mt[0][0] + t * 4;

    // flat pos region: 16 independent loads, fmin tree (exact, order-free)
    float fp[FLAT];
    #pragma unroll
    for (int j = 0; j < FLAT; j++) fp[j] = *(const float*)(mtb + posl[j]);
    float mn;
    {
        float a0 = fminf(fp[0], fp[1]),  a1 = fminf(fp[2], fp[3]);
        float a2 = fminf(fp[4], fp[5]),  a3 = fminf(fp[6], fp[7]);
        float a4 = fminf(fp[8], fp[9]),  a5 = fminf(fp[10], fp[11]);
        float a6 = fminf(fp[12], fp[13]), a7 = fminf(fp[14], fp[15]);
        mn = fminf(fminf(fminf(a0, a1), fminf(a2, a3)),
                   fminf(fminf(a4, a5), fminf(a6, a7)));
    }
    for (int k = FLAT; k < pc; k++)      // rare tail (~3%)
        mn = fminf(mn, *(const float*)(mtb + posl[k]));

    // flat neg region: 16 independent loads, fmax tree
    float fn[FLAT];
    #pragma unroll
    for (int j = 0; j < FLAT; j++) fn[j] = *(const float*)(mtb + negl[j]);
    float mx;
    {
        float a0 = fmaxf(fn[0], fn[1]),  a1 = fmaxf(fn[2], fn[3]);
        float a2 = fmaxf(fn[4], fn[5]),  a3 = fmaxf(fn[6], fn[7]);
        float a4 = fmaxf(fn[8], fn[9]),  a5 = fmaxf(fn[10], fn[11]);
        float a6 = fmaxf(fn[12], fn[13]), a7 = fmaxf(fn[14], fn[15]);
        mx = fmaxf(fmaxf(fmaxf(a0, a1), fmaxf(a2, a3)),
                   fmaxf(fmaxf(a4, a5), fmaxf(a6, a7)));
    }
    for (int k = FLAT; k < nc; k++)
        mx = fmaxf(mx, *(const float*)(mtb + negl[k]));

    // bmax = max(0, max_pos fl(1-m), max_neg m); sentinels give the 0 baseline
    const float bmax = fmaxf(1.0f - mn, mx);
    const float bmin = 1.0f - bmax;      // same op order as reference

    // fire-and-forget max reduction to head atom n (bit-pattern max, [0,1])
    const int n = (hm >> 1) & (NN - 1);
    if (hm >= 0) {
        if (hm & 1) atomicMax(&g_ub[n][t], __float_as_uint(bmin));
        else        atomicMax(&g_lb[n][t], __float_as_uint(bmin));
    }

    // release maxes, then countdown (merged arrive+count: old==1 -> last)
    __threadfence();
    __syncthreads();
    if (t == 0)
        s_last = (hm >= 0) && (atomicSub(&g_cd[n], 1) == 1);
    __syncthreads();

    // last arriver for atom n finalizes the output column + resets state
    if (s_last) {
        __threadfence();   // acquire
        const float lb = __uint_as_float(*(volatile unsigned*)&g_lb[n][t]);
        const float ub = 1.0f - __uint_as_float(*(volatile unsigned*)&g_ub[n][t]);
        const float lo = fminf(lb, ub);
        const float hi = fmaxf(lb, ub);
        out[t * NC + (atoms[n] & (NC - 1))] = fmaxf(lo, fminf(hi, g_mt[n][t]));
        g_lb[n][t] = 0u; g_ub[n][t] = 0u;   // replay-safe reset (g_cd already 0)
    }
    // atoms with no contributors: clamp is identity -> copied preds is correct
}

extern "C" void kernel_launch(void* const* d_in, const int* in_sizes, int n_in,
                              void* d_out, int out_size)
{
    const float* preds    = (const float*)d_in[0];
    const float* pos_head = (const float*)d_in[1];
    const float* neg_head = (const float*)d_in[2];
    const float* pos_body = (const float*)d_in[3];
    const float* neg_body = (const float*)d_in[4];
    const int*   atoms    = (const int*)d_in[5];
    float* out = (float*)d_out;

    k_head<<<NN, 128>>>(preds, pos_head, neg_head, atoms, out);
    k_body<<<CC, 128>>>(pos_body, neg_body, atoms, out);
}